// round 11
// baseline (speedup 1.0000x reference)
#include <cuda_runtime.h>
#include <cuda_bf16.h>
#include <math.h>
#include <stdint.h>

#define H    16
#define HD   128
#define HHD  2048   // H*HD
#define SEQ  2048
#define NT   4096   // B*S tokens
#define DIM  2048
#define QR   1536
#define KVR  512
#define NOPE 96
#define BH   32     // B*H
#define KVUP 4096   // QR + 512 + HHD

// ---------------- fp32 scratch ----------------------------------------------
__device__ float g_q[(size_t)NT * HHD];
__device__ float g_kvup[(size_t)NT * KVUP];  // [kn 0:1536 | kr 1536:2048 | v 2048:4096]

// ---------------- bf16 hi/lo scratch ----------------------------------------
__device__ __nv_bfloat16 g_x_h[(size_t)NT * DIM],  g_x_l[(size_t)NT * DIM];
__device__ __nv_bfloat16 g_qkv_h[(size_t)NT * 2048], g_qkv_l[(size_t)NT * 2048]; // [qlat|kv]
__device__ __nv_bfloat16 g_at_h[(size_t)NT * HHD], g_at_l[(size_t)NT * HHD];
// attention operands, [BH][SEQ][HD] (Q,K) and [BH][HD][SEQ] (Vt)
__device__ __nv_bfloat16 g_qa_h[(size_t)BH * SEQ * HD], g_qa_l[(size_t)BH * SEQ * HD];
__device__ __nv_bfloat16 g_ka_h[(size_t)BH * SEQ * HD], g_ka_l[(size_t)BH * SEQ * HD];
__device__ __nv_bfloat16 g_vt_h[(size_t)BH * HD * SEQ], g_vt_l[(size_t)BH * HD * SEQ];
// weights, pre-transposed to [N,K]; wA = [wq_down | wkv_down], wB = [wn|wr|wv]
__device__ __nv_bfloat16 g_wA_h[(size_t)2048 * DIM],  g_wA_l[(size_t)2048 * DIM];
__device__ __nv_bfloat16 g_wqu_h[(size_t)HHD * QR],   g_wqu_l[(size_t)HHD * QR];
__device__ __nv_bfloat16 g_wB_h[(size_t)KVUP * KVR],  g_wB_l[(size_t)KVUP * KVR];
__device__ __nv_bfloat16 g_wo_h[(size_t)DIM * HHD],   g_wo_l[(size_t)DIM * HHD];

// ---------------- helpers ----------------------------------------------------
__device__ __forceinline__ uint32_t smem_u32(const void* p) {
  uint32_t a;
  asm("{ .reg .u64 t; cvta.to.shared.u64 t, %1; cvt.u32.u64 %0, t; }"
      : "=r"(a) : "l"(p));
  return a;
}
__device__ __forceinline__ void cp16(uint32_t dst, const void* src) {
  asm volatile("cp.async.cg.shared.global [%0], [%1], 16;"
               :: "r"(dst), "l"(src) : "memory");
}
__device__ __forceinline__ void cp_commit() {
  asm volatile("cp.async.commit_group;" ::: "memory");
}
__device__ __forceinline__ void mma16816(float* c, const uint32_t* a,
                                         const uint32_t* b) {
  asm volatile(
      "mma.sync.aligned.m16n8k16.row.col.f32.bf16.bf16.f32 "
      "{%0,%1,%2,%3}, {%4,%5,%6,%7}, {%8,%9}, {%0,%1,%2,%3};"
      : "+f"(c[0]), "+f"(c[1]), "+f"(c[2]), "+f"(c[3])
      : "r"(a[0]), "r"(a[1]), "r"(a[2]), "r"(a[3]), "r"(b[0]), "r"(b[1]));
}
__device__ __forceinline__ uint32_t pack2bf(float a, float b) {
  __nv_bfloat162 t;
  t.x = __float2bfloat16(a);
  t.y = __float2bfloat16(b);
  return *reinterpret_cast<uint32_t*>(&t);
}

// ---------------- split / transpose-split conversions -----------------------
__global__ void split_kernel(const float* __restrict__ in,
                             __nv_bfloat16* __restrict__ hi,
                             __nv_bfloat16* __restrict__ lo, int n4) {
  int i = blockIdx.x * blockDim.x + threadIdx.x;
  if (i >= n4) return;
  float4 v = ((const float4*)in)[i];
  __nv_bfloat16 h0 = __float2bfloat16(v.x);
  __nv_bfloat16 h1 = __float2bfloat16(v.y);
  __nv_bfloat16 h2 = __float2bfloat16(v.z);
  __nv_bfloat16 h3 = __float2bfloat16(v.w);
  __nv_bfloat16 l0 = __float2bfloat16(v.x - __bfloat162float(h0));
  __nv_bfloat16 l1 = __float2bfloat16(v.y - __bfloat162float(h1));
  __nv_bfloat16 l2 = __float2bfloat16(v.z - __bfloat162float(h2));
  __nv_bfloat16 l3 = __float2bfloat16(v.w - __bfloat162float(h3));
  uint2 hp, lp;
  hp.x = ((uint32_t)__bfloat16_as_ushort(h1) << 16) | __bfloat16_as_ushort(h0);
  hp.y = ((uint32_t)__bfloat16_as_ushort(h3) << 16) | __bfloat16_as_ushort(h2);
  lp.x = ((uint32_t)__bfloat16_as_ushort(l1) << 16) | __bfloat16_as_ushort(l0);
  lp.y = ((uint32_t)__bfloat16_as_ushort(l3) << 16) | __bfloat16_as_ushort(l2);
  ((uint2*)hi)[i] = hp;
  ((uint2*)lo)[i] = lp;
}

// W[Kd,Nd] -> Th/Tl[Nd,Kd] (bf16 hi/lo)
__global__ void tsplit_kernel(const float* __restrict__ W,
                              __nv_bfloat16* __restrict__ Th,
                              __nv_bfloat16* __restrict__ Tl, int Kd, int Nd) {
  __shared__ float t[32][33];
  int n0 = blockIdx.x * 32, k0 = blockIdx.y * 32;
  int tx = threadIdx.x, ty = threadIdx.y;
#pragma unroll
  for (int i = 0; i < 32; i += 8)
    t[ty + i][tx] = W[(size_t)(k0 + ty + i) * Nd + n0 + tx];
  __syncthreads();
#pragma unroll
  for (int i = 0; i < 32; i += 8) {
    float v = t[tx][ty + i];
    size_t o = (size_t)(n0 + ty + i) * Kd + k0 + tx;
    __nv_bfloat16 h = __float2bfloat16(v);
    Th[o] = h;
    Tl[o] = __float2bfloat16(v - __bfloat162float(h));
  }
}

// ---------------- mma.sync bf16-split GEMM, tile 128x256 ---------------------
// C[M,N] = A[M,K] @ B[K,N]; A hi/lo bf16 [M,K] (lda), B [N,K] (ldb).
// 256 threads, 8 warps (2x4), warp tile 64x64. BK=32, double-buffered.
// Stage (bytes): Ah 0 (10240), Al 10240, Bh 20480 (20480), Bl 40960; 61440/stage.
#define MG_SMEM 122880

__device__ __forceinline__ void mg_load(uint32_t sb,
                                        const __nv_bfloat16* Ah,
                                        const __nv_bfloat16* Al,
                                        const __nv_bfloat16* Bh,
                                        const __nv_bfloat16* Bl,
                                        int lda, int ldb, int k0, int tid) {
#pragma unroll
  for (int i = 0; i < 2; i++) {
    int idx = tid + i * 256;
    int row = idx >> 2;
    int cw = (idx & 3) << 3;
    uint32_t d = sb + (uint32_t)(row * 80 + cw * 2);
    size_t ga = (size_t)row * lda + k0 + cw;
    cp16(d, Ah + ga);
    cp16(d + 10240, Al + ga);
  }
#pragma unroll
  for (int i = 0; i < 4; i++) {
    int idx = tid + i * 256;
    int row = idx >> 2;
    int cw = (idx & 3) << 3;
    uint32_t d = sb + 20480 + (uint32_t)(row * 80 + cw * 2);
    size_t gb = (size_t)row * ldb + k0 + cw;
    cp16(d, Bh + gb);
    cp16(d + 20480, Bl + gb);
  }
}

__global__ __launch_bounds__(256) void mma_gemm_kernel(
    const __nv_bfloat16* __restrict__ Ahi, const __nv_bfloat16* __restrict__ Alo,
    const __nv_bfloat16* __restrict__ Bhi, const __nv_bfloat16* __restrict__ Blo,
    float* __restrict__ Cf, __nv_bfloat16* __restrict__ Chi,
    __nv_bfloat16* __restrict__ Clo, int N, int K, int lda, int ldb,
    int split_out) {
  extern __shared__ __nv_bfloat16 smh[];
  const uint32_t sbase = smem_u32(smh);
  const int tid = threadIdx.x;
  const int warp = tid >> 5, lane = tid & 31;
  const int wm = warp >> 2, wn = warp & 3;
  const int g = lane >> 2, tg = lane & 3;
  const size_t brow = (size_t)blockIdx.y * 128;
  const size_t bcol = (size_t)blockIdx.x * 256;
  const __nv_bfloat16* Ah = Ahi + brow * lda;
  const __nv_bfloat16* Al = Alo + brow * lda;
  const __nv_bfloat16* Bh = Bhi + bcol * ldb;
  const __nv_bfloat16* Bl = Blo + bcol * ldb;

  float c[4][8][4];
#pragma unroll
  for (int mi = 0; mi < 4; mi++)
#pragma unroll
    for (int ni = 0; ni < 8; ni++)
#pragma unroll
      for (int k = 0; k < 4; k++) c[mi][ni][k] = 0.f;

  const int nk = K >> 5;
  mg_load(sbase, Ah, Al, Bh, Bl, lda, ldb, 0, tid);
  cp_commit();

  for (int it = 0; it < nk; ++it) {
    if (it + 1 < nk) {
      mg_load(sbase + ((it + 1) & 1) * 61440, Ah, Al, Bh, Bl, lda, ldb,
              (it + 1) << 5, tid);
      cp_commit();
      asm volatile("cp.async.wait_group 1;" ::: "memory");
    } else {
      asm volatile("cp.async.wait_group 0;" ::: "memory");
    }
    __syncthreads();
    const __nv_bfloat16* st = smh + (it & 1) * 30720;
#pragma unroll
    for (int kk = 0; kk < 2; kk++) {
      uint32_t ah[4][4], al[4][4];
#pragma unroll
      for (int mi = 0; mi < 4; mi++) {
        int r0 = (wm * 64 + mi * 16 + g) * 40 + kk * 16 + tg * 2;
        ah[mi][0] = *(const uint32_t*)(st + r0);
        ah[mi][1] = *(const uint32_t*)(st + r0 + 320);
        ah[mi][2] = *(const uint32_t*)(st + r0 + 8);
        ah[mi][3] = *(const uint32_t*)(st + r0 + 328);
        al[mi][0] = *(const uint32_t*)(st + 5120 + r0);
        al[mi][1] = *(const uint32_t*)(st + 5120 + r0 + 320);
        al[mi][2] = *(const uint32_t*)(st + 5120 + r0 + 8);
        al[mi][3] = *(const uint32_t*)(st + 5120 + r0 + 328);
      }
#pragma unroll
      for (int ni = 0; ni < 8; ni++) {
        int r0 = 10240 + (wn * 64 + ni * 8 + g) * 40 + kk * 16 + tg * 2;
        uint32_t bh[2], bl[2];
        bh[0] = *(const uint32_t*)(st + r0);
        bh[1] = *(const uint32_t*)(st + r0 + 8);
        bl[0] = *(const uint32_t*)(st + 10240 + r0);
        bl[1] = *(const uint32_t*)(st + 10240 + r0 + 8);
#pragma unroll
        for (int mi = 0; mi < 4; mi++) {
          mma16816(c[mi][ni], ah[mi], bh);
          mma16816(c[mi][ni], ah[mi], bl);
          mma16816(c[mi][ni], al[mi], bh);
        }
      }
    }
    __syncthreads();
  }

#pragma unroll
  for (int mi = 0; mi < 4; mi++) {
    size_t row = brow + wm * 64 + mi * 16 + g;
#pragma unroll
    for (int ni = 0; ni < 8; ni++) {
      size_t col = bcol + wn * 64 + ni * 8 + tg * 2;
      if (split_out) {
        float v0 = c[mi][ni][0], v1 = c[mi][ni][1];
        float v2 = c[mi][ni][2], v3 = c[mi][ni][3];
        float h0 = __bfloat162float(__float2bfloat16(v0));
        float h1 = __bfloat162float(__float2bfloat16(v1));
        float h2 = __bfloat162float(__float2bfloat16(v2));
        float h3 = __bfloat162float(__float2bfloat16(v3));
        *(uint32_t*)(Chi + row * N + col) = pack2bf(v0, v1);
        *(uint32_t*)(Clo + row * N + col) = pack2bf(v0 - h0, v1 - h1);
        *(uint32_t*)(Chi + (row + 8) * N + col) = pack2bf(v2, v3);
        *(uint32_t*)(Clo + (row + 8) * N + col) = pack2bf(v2 - h2, v3 - h3);
      } else {
        *(float2*)(Cf + row * N + col) =
            make_float2(c[mi][ni][0], c[mi][ni][1]);
        *(float2*)(Cf + (row + 8) * N + col) =
            make_float2(c[mi][ni][2], c[mi][ni][3]);
      }
    }
  }
}

// ---------------- q prep: rope + split + relayout to [BH][SEQ][HD] ----------
__global__ void q_prep_kernel(const float* __restrict__ q,
                              __nv_bfloat16* __restrict__ Qh,
                              __nv_bfloat16* __restrict__ Ql,
                              const float* __restrict__ cosT,
                              const float* __restrict__ sinT) {
  int idx = blockIdx.x * blockDim.x + threadIdx.x;  // BH*SEQ*64
  if (idx >= BH * SEQ * 64) return;
  int p = idx & 63;
  int s = (idx >> 6) & (SEQ - 1);
  int bh = idx >> 17;
  int b = bh >> 4, h = bh & 15;
  float2 v = *(const float2*)(q + ((size_t)(b * SEQ + s)) * HHD + h * HD + p * 2);
  if (p >= 48) {
    int j = p - 48;
    float cc = cosT[s * 16 + j], ss = sinT[s * 16 + j];
    v = make_float2(v.x * cc - v.y * ss, v.x * ss + v.y * cc);
  }
  float hx = __bfloat162float(__float2bfloat16(v.x));
  float hy = __bfloat162float(__float2bfloat16(v.y));
  size_t dst = ((size_t)bh * SEQ + s) * HD + p * 2;
  *(uint32_t*)(Qh + dst) = pack2bf(v.x, v.y);
  *(uint32_t*)(Ql + dst) = pack2bf(v.x - hx, v.y - hy);
}

// ---------------- k prep: assemble + rope + split to [BH][SEQ][HD] ----------
__global__ void k_prep_kernel(const float* __restrict__ kvup,
                              __nv_bfloat16* __restrict__ Kh,
                              __nv_bfloat16* __restrict__ Kl,
                              const float* __restrict__ cosT,
                              const float* __restrict__ sinT) {
  int idx = blockIdx.x * blockDim.x + threadIdx.x;  // BH*SEQ*64
  if (idx >= BH * SEQ * 64) return;
  int p = idx & 63;
  int s = (idx >> 6) & (SEQ - 1);
  int bh = idx >> 17;
  int b = bh >> 4, h = bh & 15;
  size_t tok = (size_t)(b * SEQ + s);
  float2 v;
  if (p < 48) {
    v = *(const float2*)(kvup + tok * KVUP + h * NOPE + p * 2);
  } else {
    int j = p - 48;
    float cc = cosT[s * 16 + j], ss = sinT[s * 16 + j];
    float2 r = *(const float2*)(kvup + tok * KVUP + QR + h * 32 + j * 2);
    v = make_float2(r.x * cc - r.y * ss, r.x * ss + r.y * cc);
  }
  float hx = __bfloat162float(__float2bfloat16(v.x));
  float hy = __bfloat162float(__float2bfloat16(v.y));
  size_t dst = ((size_t)bh * SEQ + s) * HD + p * 2;
  *(uint32_t*)(Kh + dst) = pack2bf(v.x, v.y);
  *(uint32_t*)(Kl + dst) = pack2bf(v.x - hx, v.y - hy);
}

// ---------------- v prep: transpose + split to [BH][HD][SEQ] ----------------
__global__ void vt_prep_kernel(const float* __restrict__ kvup,
                               __nv_bfloat16* __restrict__ Vh,
                               __nv_bfloat16* __restrict__ Vl) {
  __shared__ float t[32][33];
  int bh = blockIdx.z, b = bh >> 4, h = bh & 15;
  int s0 = blockIdx.x * 32, d0 = blockIdx.y * 32;
  int tx = threadIdx.x, ty = threadIdx.y;
#pragma unroll
  for (int i = 0; i < 32; i += 8)
    t[ty + i][tx] = kvup[((size_t)(b * SEQ) + s0 + ty + i) * KVUP + 2048 +
                         h * HD + d0 + tx];
  __syncthreads();
#pragma unroll
  for (int i = 0; i < 32; i += 8) {
    float val = t[tx][ty + i];
    size_t o = ((size_t)bh * HD + d0 + ty + i) * SEQ + s0 + tx;
    __nv_bfloat16 hh = __float2bfloat16(val);
    Vh[o] = hh;
    Vl[o] = __float2bfloat16(val - __bfloat162float(hh));
  }
}

// ---------------- tensor-core flash attention --------------------------------
// Q tile 128, KV tile 64; 4 warps, each warp 32 q-rows (mi=2) so K/V smem
// fragments are shared across two m-frags (halves crossbar traffic).
#define FS_QL 17408
#define FS_K0 34816
#define FS_STG 35840
#define FS_KL 8704
#define FS_VH 17408
#define FLASH_MMA_SMEM 212992

__device__ __forceinline__ void flash_load_kv(
    uint32_t sb, const __nv_bfloat16* Kh, const __nv_bfloat16* Kl,
    const __nv_bfloat16* Vth, const __nv_bfloat16* Vtl, int kb, int stg,
    int tid) {
  uint32_t base = sb + (uint32_t)(FS_K0 + stg * FS_STG) * 2;
#pragma unroll
  for (int i = 0; i < 8; i++) {
    int idx = tid + i * 128;
    int r = idx >> 4, c = (idx & 15) << 3;
    uint32_t d = base + (uint32_t)(r * 136 + c) * 2;
    size_t gsrc = (size_t)(kb * 64 + r) * HD + c;
    cp16(d, Kh + gsrc);
    cp16(d + FS_KL * 2, Kl + gsrc);
  }
#pragma unroll
  for (int i = 0; i < 8; i++) {
    int idx = tid + i * 128;
    int r = idx >> 3, c = (idx & 7) << 3;
    uint32_t d = base + FS_VH * 2 + (uint32_t)(r * 72 + c) * 2;
    size_t gsrc = (size_t)r * SEQ + kb * 64 + c;
    cp16(d, Vth + gsrc);
    cp16(d + 9216 * 2, Vtl + gsrc);
  }
}

__global__ __launch_bounds__(128) void flash_mma_kernel(
    const __nv_bfloat16* __restrict__ Qh_, const __nv_bfloat16* __restrict__ Ql_,
    const __nv_bfloat16* __restrict__ Kh_, const __nv_bfloat16* __restrict__ Kl_,
    const __nv_bfloat16* __restrict__ Vh_, const __nv_bfloat16* __restrict__ Vl_,
    __nv_bfloat16* __restrict__ Oh, __nv_bfloat16* __restrict__ Ol) {
  extern __shared__ __nv_bfloat16 fs[];
  const uint32_t sb = smem_u32(fs);
  const int qb = gridDim.x - 1 - blockIdx.x;  // big tiles first
  const int bh = blockIdx.y;
  const int b = bh >> 4, h = bh & 15;
  const int tid = threadIdx.x, warp = tid >> 5, lane = tid & 31;
  const int g = lane >> 2, tg = lane & 3;
  const __nv_bfloat16* Qh = Qh_ + ((size_t)bh * SEQ + qb * 128) * HD;
  const __nv_bfloat16* Ql = Ql_ + ((size_t)bh * SEQ + qb * 128) * HD;
  const __nv_bfloat16* Kh = Kh_ + (size_t)bh * SEQ * HD;
  const __nv_bfloat16* Kl = Kl_ + (size_t)bh * SEQ * HD;
  const __nv_bfloat16* Vh = Vh_ + (size_t)bh * HD * SEQ;
  const __nv_bfloat16* Vl = Vl_ + (size_t)bh * HD * SEQ;

#pragma unroll
  for (int i = 0; i < 16; i++) {
    int idx = tid + i * 128;
    int r = idx >> 4, c = (idx & 15) << 3;
    uint32_t d = sb + (uint32_t)(r * 136 + c) * 2;
    cp16(d, Qh + (size_t)r * HD + c);
    cp16(d + FS_QL * 2, Ql + (size_t)r * HD + c);
  }
  flash_load_kv(sb, Kh, Kl, Vh, Vl, 0, 0, tid);
  cp_commit();

  float m[2][2], l[2][2];
#pragma unroll
  for (int mi = 0; mi < 2; mi++) {
    m[mi][0] = -1e30f; m[mi][1] = -1e30f;
    l[mi][0] = 0.f;    l[mi][1] = 0.f;
  }
  float o[2][16][4];
#pragma unroll
  for (int mi = 0; mi < 2; mi++)
#pragma unroll
    for (int ni = 0; ni < 16; ni++)
#pragma unroll
      for (int k = 0; k < 4; k++) o[mi][ni][k] = 0.f;

  const int nkb = 2 * qb + 2;
  const float scale = 0.08838834764831843f;

  for (int kb = 0; kb < nkb; kb++) {
    if (kb + 1 < nkb) {
      flash_load_kv(sb, Kh, Kl, Vh, Vl, kb + 1, (kb + 1) & 1, tid);
      cp_commit();
      asm volatile("cp.async.wait_group 1;" ::: "memory");
    } else {
      asm volatile("cp.async.wait_group 0;" ::: "memory");
    }
    __syncthreads();
    const __nv_bfloat16* Ks = fs + FS_K0 + (kb & 1) * FS_STG;
    const __nv_bfloat16* Vs = Ks + FS_VH;

    // S = Q @ K^T (hi/lo split), warp rows = warp*32 + mi*16
    float c[2][8][4];
#pragma unroll
    for (int mi = 0; mi < 2; mi++)
#pragma unroll
      for (int ni = 0; ni < 8; ni++)
#pragma unroll
        for (int k = 0; k < 4; k++) c[mi][ni][k] = 0.f;
#pragma unroll
    for (int kk = 0; kk < 8; kk++) {
      uint32_t ah[2][4], al[2][4];
#pragma unroll
      for (int mi = 0; mi < 2; mi++) {
        const __nv_bfloat16* qp =
            fs + (warp * 32 + mi * 16 + g) * 136 + kk * 16 + tg * 2;
        ah[mi][0] = *(const uint32_t*)qp;
        ah[mi][1] = *(const uint32_t*)(qp + 1088);
        ah[mi][2] = *(const uint32_t*)(qp + 8);
        ah[mi][3] = *(const uint32_t*)(qp + 1096);
        al[mi][0] = *(const uint32_t*)(qp + FS_QL);
        al[mi][1] = *(const uint32_t*)(qp + FS_QL + 1088);
        al[mi][2] = *(const uint32_t*)(qp + FS_QL + 8);
        al[mi][3] = *(const uint32_t*)(qp + FS_QL + 1096);
      }
#pragma unroll
      for (int ni = 0; ni < 8; ni++) {
        const __nv_bfloat16* kp = Ks + (ni * 8 + g) * 136 + kk * 16 + tg * 2;
        uint32_t bh2[2], bl2[2];
        bh2[0] = *(const uint32_t*)kp;
        bh2[1] = *(const uint32_t*)(kp + 8);
        bl2[0] = *(const uint32_t*)(kp + FS_KL);
        bl2[1] = *(const uint32_t*)(kp + FS_KL + 8);
#pragma unroll
        for (int mi = 0; mi < 2; mi++) {
          mma16816(c[mi][ni], ah[mi], bh2);
          mma16816(c[mi][ni], al[mi], bh2);
          mma16816(c[mi][ni], ah[mi], bl2);
        }
      }
    }

    const bool msk = (kb >= 2 * qb);
#pragma unroll
    for (int mi = 0; mi < 2; mi++) {
      const int rg0 = qb * 128 + warp * 32 + mi * 16 + g;
      const int rg1 = rg0 + 8;
      float mx0 = -1e30f, mx1 = -1e30f;
#pragma unroll
      for (int ni = 0; ni < 8; ni++) {
        int cg = kb * 64 + ni * 8 + tg * 2;
        float t0 = c[mi][ni][0] * scale, t1 = c[mi][ni][1] * scale;
        float t2 = c[mi][ni][2] * scale, t3 = c[mi][ni][3] * scale;
        if (msk) {
          if (cg > rg0) t0 = -1e30f;
          if (cg + 1 > rg0) t1 = -1e30f;
          if (cg > rg1) t2 = -1e30f;
          if (cg + 1 > rg1) t3 = -1e30f;
        }
        c[mi][ni][0] = t0; c[mi][ni][1] = t1;
        c[mi][ni][2] = t2; c[mi][ni][3] = t3;
        mx0 = fmaxf(mx0, fmaxf(t0, t1));
        mx1 = fmaxf(mx1, fmaxf(t2, t3));
      }
      mx0 = fmaxf(mx0, __shfl_xor_sync(0xffffffffu, mx0, 1));
      mx0 = fmaxf(mx0, __shfl_xor_sync(0xffffffffu, mx0, 2));
      mx1 = fmaxf(mx1, __shfl_xor_sync(0xffffffffu, mx1, 1));
      mx1 = fmaxf(mx1, __shfl_xor_sync(0xffffffffu, mx1, 2));

      float mn0 = fmaxf(m[mi][0], mx0), mn1 = fmaxf(m[mi][1], mx1);
      float corr0 = __expf(m[mi][0] - mn0), corr1 = __expf(m[mi][1] - mn1);
      m[mi][0] = mn0; m[mi][1] = mn1;
      float s0 = 0.f, s1 = 0.f;
#pragma unroll
      for (int ni = 0; ni < 8; ni++) {
        c[mi][ni][0] = __expf(c[mi][ni][0] - mn0);
        c[mi][ni][1] = __expf(c[mi][ni][1] - mn0);
        c[mi][ni][2] = __expf(c[mi][ni][2] - mn1);
        c[mi][ni][3] = __expf(c[mi][ni][3] - mn1);
        s0 += c[mi][ni][0] + c[mi][ni][1];
        s1 += c[mi][ni][2] + c[mi][ni][3];
      }
      s0 += __shfl_xor_sync(0xffffffffu, s0, 1);
      s0 += __shfl_xor_sync(0xffffffffu, s0, 2);
      s1 += __shfl_xor_sync(0xffffffffu, s1, 1);
      s1 += __shfl_xor_sync(0xffffffffu, s1, 2);
      l[mi][0] = l[mi][0] * corr0 + s0;
      l[mi][1] = l[mi][1] * corr1 + s1;
#pragma unroll
      for (int ni = 0; ni < 16; ni++) {
        o[mi][ni][0] *= corr0; o[mi][ni][1] *= corr0;
        o[mi][ni][2] *= corr1; o[mi][ni][3] *= corr1;
      }
    }

    // O += P @ V ; V fragments loaded once per (kc,ni), shared across mi
#pragma unroll
    for (int kc = 0; kc < 4; kc++) {
      uint32_t ap[2][4], apl[2][4];
#pragma unroll
      for (int mi = 0; mi < 2; mi++) {
        float p00 = c[mi][2 * kc][0], p01 = c[mi][2 * kc][1];
        float p02 = c[mi][2 * kc][2], p03 = c[mi][2 * kc][3];
        float p10 = c[mi][2 * kc + 1][0], p11 = c[mi][2 * kc + 1][1];
        float p12 = c[mi][2 * kc + 1][2], p13 = c[mi][2 * kc + 1][3];
        ap[mi][0] = pack2bf(p00, p01);
        ap[mi][1] = pack2bf(p02, p03);
        ap[mi][2] = pack2bf(p10, p11);
        ap[mi][3] = pack2bf(p12, p13);
        float h00 = __bfloat162float(__float2bfloat16(p00));
        float h01 = __bfloat162float(__float2bfloat16(p01));
        float h02 = __bfloat162float(__float2bfloat16(p02));
        float h03 = __bfloat162float(__float2bfloat16(p03));
        float h10 = __bfloat162float(__float2bfloat16(p10));
        float h11 = __bfloat162float(__float2bfloat16(p11));
        float h12 = __bfloat162float(__float2bfloat16(p12));
        float h13 = __bfloat162float(__float2bfloat16(p13));
        apl[mi][0] = pack2bf(p00 - h00, p01 - h01);
        apl[mi][1] = pack2bf(p02 - h02, p03 - h03);
        apl[mi][2] = pack2bf(p10 - h10, p11 - h11);
        apl[mi][3] = pack2bf(p12 - h12, p13 - h13);
      }
#pragma unroll
      for (int ni = 0; ni < 16; ni++) {
        const __nv_bfloat16* vp = Vs + (ni * 8 + g) * 72 + kc * 16 + tg * 2;
        uint32_t bv[2], bvl[2];
        bv[0] = *(const uint32_t*)vp;
        bv[1] = *(const uint32_t*)(vp + 8);
        bvl[0] = *(const uint32_t*)(vp + 9216);
        bvl[1] = *(const uint32_t*)(vp + 9216 + 8);
#pragma unroll
        for (int mi = 0; mi < 2; mi++) {
          mma16816(o[mi][ni], ap[mi], bv);
          mma16816(o[mi][ni], apl[mi], bv);
          mma16816(o[mi][ni], ap[mi], bvl);
        }
      }
    }
    __syncthreads();
  }

  // epilogue: normalize, split to bf16 hi/lo, write [tok][HHD]
#pragma unroll
  for (int mi = 0; mi < 2; mi++) {
    const float inv0 = 1.f / l[mi][0], inv1 = 1.f / l[mi][1];
    const size_t row0 = (size_t)b * SEQ + qb * 128 + warp * 32 + mi * 16 + g;
#pragma unroll
    for (int ni = 0; ni < 16; ni++) {
      int col = h * HD + ni * 8 + tg * 2;
      float v0 = o[mi][ni][0] * inv0, v1 = o[mi][ni][1] * inv0;
      float v2 = o[mi][ni][2] * inv1, v3 = o[mi][ni][3] * inv1;
      float h0 = __bfloat162float(__float2bfloat16(v0));
      float h1 = __bfloat162float(__float2bfloat16(v1));
      float h2 = __bfloat162float(__float2bfloat16(v2));
      float h3 = __bfloat162float(__float2bfloat16(v3));
      size_t i0 = row0 * HHD + col;
      size_t i1 = (row0 + 8) * HHD + col;
      *(uint32_t*)(Oh + i0) = pack2bf(v0, v1);
      *(uint32_t*)(Ol + i0) = pack2bf(v0 - h0, v1 - h1);
      *(uint32_t*)(Oh + i1) = pack2bf(v2, v3);
      *(uint32_t*)(Ol + i1) = pack2bf(v2 - h2, v3 - h3);
    }
  }
}

// ---------------- launch -----------------------------------------------------
#define SYM(p, s)                          \
  do {                                     \
    void* _t;                              \
    cudaGetSymbolAddress(&_t, s);          \
    p = (decltype(p))_t;                   \
  } while (0)

extern "C" void kernel_launch(void* const* d_in, const int* in_sizes, int n_in,
                              void* d_out, int out_size) {
  const float* x = (const float*)d_in[0];
  const float* cosT = (const float*)d_in[1];
  const float* sinT = (const float*)d_in[2];
  const float* wq_down = (const float*)d_in[3];
  const float* wq_up = (const float*)d_in[4];
  const float* wkv_down = (const float*)d_in[5];
  const float* w_nope = (const float*)d_in[6];
  const float* w_rope = (const float*)d_in[7];
  const float* w_val = (const float*)d_in[8];
  const float* wo = (const float*)d_in[9];
  float* out = (float*)d_out;

  float *p_q, *p_kvup;
  SYM(p_q, g_q); SYM(p_kvup, g_kvup);

  __nv_bfloat16 *xh, *xl, *qkvh, *qkvl, *ath, *atl;
  __nv_bfloat16 *qah, *qal, *kah, *kal, *vth, *vtl;
  __nv_bfloat16 *wAh, *wAl, *wquh, *wqul, *wBh, *wBl, *woh, *wol;
  SYM(xh, g_x_h);   SYM(xl, g_x_l);
  SYM(qkvh, g_qkv_h); SYM(qkvl, g_qkv_l);
  SYM(ath, g_at_h); SYM(atl, g_at_l);
  SYM(qah, g_qa_h); SYM(qal, g_qa_l); SYM(kah, g_ka_h); SYM(kal, g_ka_l);
  SYM(vth, g_vt_h); SYM(vtl, g_vt_l);
  SYM(wAh, g_wA_h); SYM(wAl, g_wA_l); SYM(wquh, g_wqu_h); SYM(wqul, g_wqu_l);
  SYM(wBh, g_wB_h); SYM(wBl, g_wB_l); SYM(woh, g_wo_h);  SYM(wol, g_wo_l);

  cudaFuncSetAttribute(mma_gemm_kernel,
                       cudaFuncAttributeMaxDynamicSharedMemorySize, MG_SMEM);
  cudaFuncSetAttribute(flash_mma_kernel,
                       cudaFuncAttributeMaxDynamicSharedMemorySize,
                       FLASH_MMA_SMEM);

  dim3 tsb(32, 8);
  // input/weight conversions (wA = [wq_down | wkv_down], wB = [wn|wr|wv])
  split_kernel<<<(NT * DIM / 4) / 256, 256>>>(x, xh, xl, NT * DIM / 4);
  tsplit_kernel<<<dim3(QR / 32, DIM / 32), tsb>>>(wq_down, wAh, wAl, DIM, QR);
  tsplit_kernel<<<dim3(KVR / 32, DIM / 32), tsb>>>(
      wkv_down, wAh + (size_t)QR * DIM, wAl + (size_t)QR * DIM, DIM, KVR);
  tsplit_kernel<<<dim3(HHD / 32, QR / 32), tsb>>>(wq_up, wquh, wqul, QR, HHD);
  tsplit_kernel<<<dim3(QR / 32, KVR / 32), tsb>>>(w_nope, wBh, wBl, KVR, QR);
  tsplit_kernel<<<dim3(512 / 32, KVR / 32), tsb>>>(
      w_rope, wBh + (size_t)QR * KVR, wBl + (size_t)QR * KVR, KVR, 512);
  tsplit_kernel<<<dim3(HHD / 32, KVR / 32), tsb>>>(
      w_val, wBh + (size_t)2048 * KVR, wBl + (size_t)2048 * KVR, KVR, HHD);
  tsplit_kernel<<<dim3(DIM / 32, HHD / 32), tsb>>>(wo, woh, wol, HHD, DIM);

  // G1: x @ [wq_down|wkv_down] -> qkv hi/lo bf16 [NT, 2048]
  mma_gemm_kernel<<<dim3(2048 / 256, NT / 128), 256, MG_SMEM>>>(
      xh, xl, wAh, wAl, nullptr, qkvh, qkvl, 2048, DIM, DIM, DIM, 1);
  // G2: qlat @ wq_up -> p_q fp32
  mma_gemm_kernel<<<dim3(HHD / 256, NT / 128), 256, MG_SMEM>>>(
      qkvh, qkvl, wquh, wqul, p_q, nullptr, nullptr, HHD, QR, 2048, QR, 0);
  // G3: kv @ [wn|wr|wv] -> p_kvup fp32 [NT, 4096]
  mma_gemm_kernel<<<dim3(KVUP / 256, NT / 128), 256, MG_SMEM>>>(
      qkvh + QR, qkvl + QR, wBh, wBl, p_kvup, nullptr, nullptr, KVUP, KVR,
      2048, KVR, 0);

  // attention operand prep
  q_prep_kernel<<<(BH * SEQ * 64) / 256, 256>>>(p_q, qah, qal, cosT, sinT);
  k_prep_kernel<<<(BH * SEQ * 64) / 256, 256>>>(p_kvup, kah, kal, cosT, sinT);
  vt_prep_kernel<<<dim3(SEQ / 32, HD / 32, BH), tsb>>>(p_kvup, vth, vtl);

  // attention (writes bf16 hi/lo directly)
  flash_mma_kernel<<<dim3(SEQ / 128, BH), 128, FLASH_MMA_SMEM>>>(
      qah, qal, kah, kal, vth, vtl, ath, atl);

  // G4: attn @ wo -> out fp32
  mma_gemm_kernel<<<dim3(DIM / 256, NT / 128), 256, MG_SMEM>>>(
      ath, atl, woh, wol, out, nullptr, nullptr, DIM, HHD, HHD, HHD, 0);
}

// round 13
// speedup vs baseline: 1.1398x; 1.1398x over previous
#include <cuda_runtime.h>
#include <cuda_bf16.h>
#include <math.h>
#include <stdint.h>

#define H    16
#define HD   128
#define HHD  2048   // H*HD
#define SEQ  2048
#define NT   4096   // B*S tokens
#define DIM  2048
#define QR   1536
#define KVR  512
#define NOPE 96
#define BH   32     // B*H
#define KVUP 4096   // QR + 512 + HHD

// ---------------- fp32 scratch ----------------------------------------------
__device__ float g_q[(size_t)NT * HHD];
__device__ float g_kvup[(size_t)NT * KVUP];  // [kn 0:1536 | kr 1536:2048 | v 2048:4096]

// ---------------- bf16 hi/lo scratch ----------------------------------------
__device__ __nv_bfloat16 g_x_h[(size_t)NT * DIM],  g_x_l[(size_t)NT * DIM];
__device__ __nv_bfloat16 g_qkv_h[(size_t)NT * 2048], g_qkv_l[(size_t)NT * 2048]; // [qlat|kv]
__device__ __nv_bfloat16 g_at_h[(size_t)NT * HHD], g_at_l[(size_t)NT * HHD];
// attention operands, [BH][SEQ][HD] (Q,K) and [BH][HD][SEQ] (Vt)
__device__ __nv_bfloat16 g_qa_h[(size_t)BH * SEQ * HD], g_qa_l[(size_t)BH * SEQ * HD];
__device__ __nv_bfloat16 g_ka_h[(size_t)BH * SEQ * HD], g_ka_l[(size_t)BH * SEQ * HD];
__device__ __nv_bfloat16 g_vt_h[(size_t)BH * HD * SEQ], g_vt_l[(size_t)BH * HD * SEQ];
// weights, pre-transposed to [N,K]; wA = [wq_down | wkv_down], wB = [wn|wr|wv]
__device__ __nv_bfloat16 g_wA_h[(size_t)2048 * DIM],  g_wA_l[(size_t)2048 * DIM];
__device__ __nv_bfloat16 g_wqu_h[(size_t)HHD * QR],   g_wqu_l[(size_t)HHD * QR];
__device__ __nv_bfloat16 g_wB_h[(size_t)KVUP * KVR],  g_wB_l[(size_t)KVUP * KVR];
__device__ __nv_bfloat16 g_wo_h[(size_t)DIM * HHD],   g_wo_l[(size_t)DIM * HHD];

// ---------------- helpers ----------------------------------------------------
__device__ __forceinline__ uint32_t smem_u32(const void* p) {
  uint32_t a;
  asm("{ .reg .u64 t; cvta.to.shared.u64 t, %1; cvt.u32.u64 %0, t; }"
      : "=r"(a) : "l"(p));
  return a;
}
__device__ __forceinline__ void cp16(uint32_t dst, const void* src) {
  asm volatile("cp.async.cg.shared.global [%0], [%1], 16;"
               :: "r"(dst), "l"(src) : "memory");
}
__device__ __forceinline__ void cp_commit() {
  asm volatile("cp.async.commit_group;" ::: "memory");
}
__device__ __forceinline__ void mma16816(float* c, const uint32_t* a,
                                         const uint32_t* b) {
  asm volatile(
      "mma.sync.aligned.m16n8k16.row.col.f32.bf16.bf16.f32 "
      "{%0,%1,%2,%3}, {%4,%5,%6,%7}, {%8,%9}, {%0,%1,%2,%3};"
      : "+f"(c[0]), "+f"(c[1]), "+f"(c[2]), "+f"(c[3])
      : "r"(a[0]), "r"(a[1]), "r"(a[2]), "r"(a[3]), "r"(b[0]), "r"(b[1]));
}
__device__ __forceinline__ void ldsm_x4(uint32_t* r, uint32_t addr) {
  asm volatile(
      "ldmatrix.sync.aligned.m8n8.x4.shared.b16 {%0,%1,%2,%3}, [%4];"
      : "=r"(r[0]), "=r"(r[1]), "=r"(r[2]), "=r"(r[3]) : "r"(addr));
}
__device__ __forceinline__ uint32_t pack2bf(float a, float b) {
  __nv_bfloat162 t;
  t.x = __float2bfloat16(a);
  t.y = __float2bfloat16(b);
  return *reinterpret_cast<uint32_t*>(&t);
}

// ---------------- split / transpose-split conversions -----------------------
__global__ void split_kernel(const float* __restrict__ in,
                             __nv_bfloat16* __restrict__ hi,
                             __nv_bfloat16* __restrict__ lo, int n4) {
  int i = blockIdx.x * blockDim.x + threadIdx.x;
  if (i >= n4) return;
  float4 v = ((const float4*)in)[i];
  __nv_bfloat16 h0 = __float2bfloat16(v.x);
  __nv_bfloat16 h1 = __float2bfloat16(v.y);
  __nv_bfloat16 h2 = __float2bfloat16(v.z);
  __nv_bfloat16 h3 = __float2bfloat16(v.w);
  __nv_bfloat16 l0 = __float2bfloat16(v.x - __bfloat162float(h0));
  __nv_bfloat16 l1 = __float2bfloat16(v.y - __bfloat162float(h1));
  __nv_bfloat16 l2 = __float2bfloat16(v.z - __bfloat162float(h2));
  __nv_bfloat16 l3 = __float2bfloat16(v.w - __bfloat162float(h3));
  uint2 hp, lp;
  hp.x = ((uint32_t)__bfloat16_as_ushort(h1) << 16) | __bfloat16_as_ushort(h0);
  hp.y = ((uint32_t)__bfloat16_as_ushort(h3) << 16) | __bfloat16_as_ushort(h2);
  lp.x = ((uint32_t)__bfloat16_as_ushort(l1) << 16) | __bfloat16_as_ushort(l0);
  lp.y = ((uint32_t)__bfloat16_as_ushort(l3) << 16) | __bfloat16_as_ushort(l2);
  ((uint2*)hi)[i] = hp;
  ((uint2*)lo)[i] = lp;
}

// W[Kd,Nd] -> Th/Tl[Nd,Kd] (bf16 hi/lo)
__global__ void tsplit_kernel(const float* __restrict__ W,
                              __nv_bfloat16* __restrict__ Th,
                              __nv_bfloat16* __restrict__ Tl, int Kd, int Nd) {
  __shared__ float t[32][33];
  int n0 = blockIdx.x * 32, k0 = blockIdx.y * 32;
  int tx = threadIdx.x, ty = threadIdx.y;
#pragma unroll
  for (int i = 0; i < 32; i += 8)
    t[ty + i][tx] = W[(size_t)(k0 + ty + i) * Nd + n0 + tx];
  __syncthreads();
#pragma unroll
  for (int i = 0; i < 32; i += 8) {
    float v = t[tx][ty + i];
    size_t o = (size_t)(n0 + ty + i) * Kd + k0 + tx;
    __nv_bfloat16 h = __float2bfloat16(v);
    Th[o] = h;
    Tl[o] = __float2bfloat16(v - __bfloat162float(h));
  }
}

// ---------------- mma.sync bf16-split GEMM, tile 128x128 (R10 shape) --------
// Fragment loads via ldmatrix.x4. Stage (bytes): Ah 0, Al 10240, Bh 20480,
// Bl 30720; stride 40960. Rows padded to 40 halves (80B), conflict-free.
#define MG_SMEM 81920

__device__ __forceinline__ void mg_load(uint32_t sb,
                                        const __nv_bfloat16* Ah,
                                        const __nv_bfloat16* Al,
                                        const __nv_bfloat16* Bh,
                                        const __nv_bfloat16* Bl,
                                        int lda, int ldb, int k0, int tid) {
#pragma unroll
  for (int i = 0; i < 2; i++) {
    int idx = tid + i * 256;
    int row = idx >> 2;
    int cw = (idx & 3) << 3;
    uint32_t d = sb + (uint32_t)(row * 80 + cw * 2);
    size_t ga = (size_t)row * lda + k0 + cw;
    size_t gb = (size_t)row * ldb + k0 + cw;
    cp16(d, Ah + ga);
    cp16(d + 10240, Al + ga);
    cp16(d + 20480, Bh + gb);
    cp16(d + 30720, Bl + gb);
  }
}

__global__ __launch_bounds__(256) void mma_gemm_kernel(
    const __nv_bfloat16* __restrict__ Ahi, const __nv_bfloat16* __restrict__ Alo,
    const __nv_bfloat16* __restrict__ Bhi, const __nv_bfloat16* __restrict__ Blo,
    float* __restrict__ Cf, __nv_bfloat16* __restrict__ Chi,
    __nv_bfloat16* __restrict__ Clo, int N, int K, int lda, int ldb,
    int split_out) {
  extern __shared__ __nv_bfloat16 smh[];
  const uint32_t sbase = smem_u32(smh);
  const int tid = threadIdx.x;
  const int warp = tid >> 5, lane = tid & 31;
  const int wm = warp >> 2, wn = warp & 3;
  const int g = lane >> 2, tg = lane & 3;
  const size_t brow = (size_t)blockIdx.y * 128;
  const size_t bcol = (size_t)blockIdx.x * 128;
  const __nv_bfloat16* Ah = Ahi + brow * lda;
  const __nv_bfloat16* Al = Alo + brow * lda;
  const __nv_bfloat16* Bh = Bhi + bcol * ldb;
  const __nv_bfloat16* Bl = Blo + bcol * ldb;

  // ldmatrix lane address components
  const int a_row = lane & 15, a_ko = (lane >> 4) << 3;
  const int b_row = ((lane >> 4) << 3) + (lane & 7);
  const int b_ko = ((lane >> 3) & 1) << 3;

  float c[4][4][4];
#pragma unroll
  for (int mi = 0; mi < 4; mi++)
#pragma unroll
    for (int ni = 0; ni < 4; ni++)
#pragma unroll
      for (int k = 0; k < 4; k++) c[mi][ni][k] = 0.f;

  const int nk = K >> 5;
  mg_load(sbase, Ah, Al, Bh, Bl, lda, ldb, 0, tid);
  cp_commit();

  for (int it = 0; it < nk; ++it) {
    if (it + 1 < nk) {
      mg_load(sbase + ((it + 1) & 1) * 40960, Ah, Al, Bh, Bl, lda, ldb,
              (it + 1) << 5, tid);
      cp_commit();
      asm volatile("cp.async.wait_group 1;" ::: "memory");
    } else {
      asm volatile("cp.async.wait_group 0;" ::: "memory");
    }
    __syncthreads();
    const uint32_t stgb = sbase + (it & 1) * 40960;
#pragma unroll
    for (int kk = 0; kk < 2; kk++) {
      uint32_t ah[4][4], al[4][4];
#pragma unroll
      for (int mi = 0; mi < 4; mi++) {
        uint32_t ar = stgb + (uint32_t)(((wm * 64 + mi * 16 + a_row) * 40 +
                                         kk * 16 + a_ko) * 2);
        ldsm_x4(ah[mi], ar);
        ldsm_x4(al[mi], ar + 10240);
      }
#pragma unroll
      for (int pi = 0; pi < 2; pi++) {
        uint32_t br = stgb + 20480 +
            (uint32_t)(((wn * 32 + pi * 16 + b_row) * 40 + kk * 16 + b_ko) * 2);
        uint32_t bhp[4], blp[4];
        ldsm_x4(bhp, br);
        ldsm_x4(blp, br + 10240);
#pragma unroll
        for (int mi = 0; mi < 4; mi++) {
          mma16816(c[mi][2 * pi], ah[mi], bhp);
          mma16816(c[mi][2 * pi], ah[mi], blp);
          mma16816(c[mi][2 * pi], al[mi], bhp);
          mma16816(c[mi][2 * pi + 1], ah[mi], bhp + 2);
          mma16816(c[mi][2 * pi + 1], ah[mi], blp + 2);
          mma16816(c[mi][2 * pi + 1], al[mi], bhp + 2);
        }
      }
    }
    __syncthreads();
  }

#pragma unroll
  for (int mi = 0; mi < 4; mi++) {
    size_t row = brow + wm * 64 + mi * 16 + g;
#pragma unroll
    for (int ni = 0; ni < 4; ni++) {
      size_t col = bcol + wn * 32 + ni * 8 + tg * 2;
      if (split_out) {
        float v0 = c[mi][ni][0], v1 = c[mi][ni][1];
        float v2 = c[mi][ni][2], v3 = c[mi][ni][3];
        float h0 = __bfloat162float(__float2bfloat16(v0));
        float h1 = __bfloat162float(__float2bfloat16(v1));
        float h2 = __bfloat162float(__float2bfloat16(v2));
        float h3 = __bfloat162float(__float2bfloat16(v3));
        *(uint32_t*)(Chi + row * N + col) = pack2bf(v0, v1);
        *(uint32_t*)(Clo + row * N + col) = pack2bf(v0 - h0, v1 - h1);
        *(uint32_t*)(Chi + (row + 8) * N + col) = pack2bf(v2, v3);
        *(uint32_t*)(Clo + (row + 8) * N + col) = pack2bf(v2 - h2, v3 - h3);
      } else {
        *(float2*)(Cf + row * N + col) =
            make_float2(c[mi][ni][0], c[mi][ni][1]);
        *(float2*)(Cf + (row + 8) * N + col) =
            make_float2(c[mi][ni][2], c[mi][ni][3]);
      }
    }
  }
}

// ---------------- q prep: rope + split + relayout to [BH][SEQ][HD] ----------
__global__ void q_prep_kernel(const float* __restrict__ q,
                              __nv_bfloat16* __restrict__ Qh,
                              __nv_bfloat16* __restrict__ Ql,
                              const float* __restrict__ cosT,
                              const float* __restrict__ sinT) {
  int idx = blockIdx.x * blockDim.x + threadIdx.x;  // BH*SEQ*64
  if (idx >= BH * SEQ * 64) return;
  int p = idx & 63;
  int s = (idx >> 6) & (SEQ - 1);
  int bh = idx >> 17;
  int b = bh >> 4, h = bh & 15;
  float2 v = *(const float2*)(q + ((size_t)(b * SEQ + s)) * HHD + h * HD + p * 2);
  if (p >= 48) {
    int j = p - 48;
    float cc = cosT[s * 16 + j], ss = sinT[s * 16 + j];
    v = make_float2(v.x * cc - v.y * ss, v.x * ss + v.y * cc);
  }
  float hx = __bfloat162float(__float2bfloat16(v.x));
  float hy = __bfloat162float(__float2bfloat16(v.y));
  size_t dst = ((size_t)bh * SEQ + s) * HD + p * 2;
  *(uint32_t*)(Qh + dst) = pack2bf(v.x, v.y);
  *(uint32_t*)(Ql + dst) = pack2bf(v.x - hx, v.y - hy);
}

// ---------------- k prep: assemble + rope + split to [BH][SEQ][HD] ----------
__global__ void k_prep_kernel(const float* __restrict__ kvup,
                              __nv_bfloat16* __restrict__ Kh,
                              __nv_bfloat16* __restrict__ Kl,
                              const float* __restrict__ cosT,
                              const float* __restrict__ sinT) {
  int idx = blockIdx.x * blockDim.x + threadIdx.x;  // BH*SEQ*64
  if (idx >= BH * SEQ * 64) return;
  int p = idx & 63;
  int s = (idx >> 6) & (SEQ - 1);
  int bh = idx >> 17;
  int b = bh >> 4, h = bh & 15;
  size_t tok = (size_t)(b * SEQ + s);
  float2 v;
  if (p < 48) {
    v = *(const float2*)(kvup + tok * KVUP + h * NOPE + p * 2);
  } else {
    int j = p - 48;
    float cc = cosT[s * 16 + j], ss = sinT[s * 16 + j];
    float2 r = *(const float2*)(kvup + tok * KVUP + QR + h * 32 + j * 2);
    v = make_float2(r.x * cc - r.y * ss, r.x * ss + r.y * cc);
  }
  float hx = __bfloat162float(__float2bfloat16(v.x));
  float hy = __bfloat162float(__float2bfloat16(v.y));
  size_t dst = ((size_t)bh * SEQ + s) * HD + p * 2;
  *(uint32_t*)(Kh + dst) = pack2bf(v.x, v.y);
  *(uint32_t*)(Kl + dst) = pack2bf(v.x - hx, v.y - hy);
}

// ---------------- v prep: transpose + split to [BH][HD][SEQ] ----------------
__global__ void vt_prep_kernel(const float* __restrict__ kvup,
                               __nv_bfloat16* __restrict__ Vh,
                               __nv_bfloat16* __restrict__ Vl) {
  __shared__ float t[32][33];
  int bh = blockIdx.z, b = bh >> 4, h = bh & 15;
  int s0 = blockIdx.x * 32, d0 = blockIdx.y * 32;
  int tx = threadIdx.x, ty = threadIdx.y;
#pragma unroll
  for (int i = 0; i < 32; i += 8)
    t[ty + i][tx] = kvup[((size_t)(b * SEQ) + s0 + ty + i) * KVUP + 2048 +
                         h * HD + d0 + tx];
  __syncthreads();
#pragma unroll
  for (int i = 0; i < 32; i += 8) {
    float val = t[tx][ty + i];
    size_t o = ((size_t)bh * HD + d0 + ty + i) * SEQ + s0 + tx;
    __nv_bfloat16 hh = __float2bfloat16(val);
    Vh[o] = hh;
    Vl[o] = __float2bfloat16(val - __bfloat162float(hh));
  }
}

// ---------------- tensor-core flash attention (R10 shape + ldmatrix) --------
#define FS_QL 17408
#define FS_K0 34816
#define FS_STG 35840
#define FS_KL 8704
#define FS_VH 17408
#define FLASH_MMA_SMEM 212992

__device__ __forceinline__ void flash_load_kv(
    uint32_t sb, const __nv_bfloat16* Kh, const __nv_bfloat16* Kl,
    const __nv_bfloat16* Vth, const __nv_bfloat16* Vtl, int kb, int stg,
    int tid) {
  uint32_t base = sb + (uint32_t)(FS_K0 + stg * FS_STG) * 2;
#pragma unroll
  for (int i = 0; i < 4; i++) {
    int idx = tid + i * 256;
    int r = idx >> 4, c = (idx & 15) << 3;
    uint32_t d = base + (uint32_t)(r * 136 + c) * 2;
    size_t gsrc = (size_t)(kb * 64 + r) * HD + c;
    cp16(d, Kh + gsrc);
    cp16(d + FS_KL * 2, Kl + gsrc);
  }
#pragma unroll
  for (int i = 0; i < 4; i++) {
    int idx = tid + i * 256;
    int r = idx >> 3, c = (idx & 7) << 3;
    uint32_t d = base + FS_VH * 2 + (uint32_t)(r * 72 + c) * 2;
    size_t gsrc = (size_t)r * SEQ + kb * 64 + c;
    cp16(d, Vth + gsrc);
    cp16(d + 9216 * 2, Vtl + gsrc);
  }
}

__global__ __launch_bounds__(256) void flash_mma_kernel(
    const __nv_bfloat16* __restrict__ Qh_, const __nv_bfloat16* __restrict__ Ql_,
    const __nv_bfloat16* __restrict__ Kh_, const __nv_bfloat16* __restrict__ Kl_,
    const __nv_bfloat16* __restrict__ Vh_, const __nv_bfloat16* __restrict__ Vl_,
    __nv_bfloat16* __restrict__ Oh, __nv_bfloat16* __restrict__ Ol) {
  extern __shared__ __nv_bfloat16 fs[];
  const uint32_t sb = smem_u32(fs);
  const int qb = gridDim.x - 1 - blockIdx.x;  // big tiles first
  const int bh = blockIdx.y;
  const int b = bh >> 4, h = bh & 15;
  const int tid = threadIdx.x, warp = tid >> 5, lane = tid & 31;
  const int g = lane >> 2, tg = lane & 3;
  const __nv_bfloat16* Qh = Qh_ + ((size_t)bh * SEQ + qb * 128) * HD;
  const __nv_bfloat16* Ql = Ql_ + ((size_t)bh * SEQ + qb * 128) * HD;
  const __nv_bfloat16* Kh = Kh_ + (size_t)bh * SEQ * HD;
  const __nv_bfloat16* Kl = Kl_ + (size_t)bh * SEQ * HD;
  const __nv_bfloat16* Vh = Vh_ + (size_t)bh * HD * SEQ;
  const __nv_bfloat16* Vl = Vl_ + (size_t)bh * HD * SEQ;

  const int a_row = lane & 15, a_ko = (lane >> 4) << 3;
  const int b_row = ((lane >> 4) << 3) + (lane & 7);
  const int b_ko = ((lane >> 3) & 1) << 3;

#pragma unroll
  for (int i = 0; i < 8; i++) {
    int idx = tid + i * 256;
    int r = idx >> 4, c = (idx & 15) << 3;
    uint32_t d = sb + (uint32_t)(r * 136 + c) * 2;
    cp16(d, Qh + (size_t)r * HD + c);
    cp16(d + FS_QL * 2, Ql + (size_t)r * HD + c);
  }
  flash_load_kv(sb, Kh, Kl, Vh, Vl, 0, 0, tid);
  cp_commit();

  float m0 = -1e30f, m1 = -1e30f, l0 = 0.f, l1 = 0.f;
  float o[16][4];
#pragma unroll
  for (int ni = 0; ni < 16; ni++)
#pragma unroll
    for (int k = 0; k < 4; k++) o[ni][k] = 0.f;

  const int nkb = 2 * qb + 2;
  const int rg0 = qb * 128 + warp * 16 + g;
  const int rg1 = rg0 + 8;
  const float scale = 0.08838834764831843f;

  for (int kb = 0; kb < nkb; kb++) {
    if (kb + 1 < nkb) {
      flash_load_kv(sb, Kh, Kl, Vh, Vl, kb + 1, (kb + 1) & 1, tid);
      cp_commit();
      asm volatile("cp.async.wait_group 1;" ::: "memory");
    } else {
      asm volatile("cp.async.wait_group 0;" ::: "memory");
    }
    __syncthreads();
    const uint32_t ksb = sb + (uint32_t)(FS_K0 + (kb & 1) * FS_STG) * 2;
    const uint32_t vsb = ksb + FS_VH * 2;

    // S = Q @ K^T (hi/lo split), ldmatrix fragments
    float c[8][4];
#pragma unroll
    for (int ni = 0; ni < 8; ni++)
#pragma unroll
      for (int k = 0; k < 4; k++) c[ni][k] = 0.f;
#pragma unroll
    for (int kk = 0; kk < 8; kk++) {
      uint32_t ah[4], al[4];
      uint32_t qa = sb + (uint32_t)(((warp * 16 + a_row) * 136 +
                                     kk * 16 + a_ko) * 2);
      ldsm_x4(ah, qa);
      ldsm_x4(al, qa + FS_QL * 2);
#pragma unroll
      for (int pi = 0; pi < 4; pi++) {
        uint32_t ka = ksb + (uint32_t)(((pi * 16 + b_row) * 136 +
                                        kk * 16 + b_ko) * 2);
        uint32_t bhp[4], blp[4];
        ldsm_x4(bhp, ka);
        ldsm_x4(blp, ka + FS_KL * 2);
        mma16816(c[2 * pi], ah, bhp);
        mma16816(c[2 * pi], al, bhp);
        mma16816(c[2 * pi], ah, blp);
        mma16816(c[2 * pi + 1], ah, bhp + 2);
        mma16816(c[2 * pi + 1], al, bhp + 2);
        mma16816(c[2 * pi + 1], ah, blp + 2);
      }
    }

    const bool msk = (kb >= 2 * qb);
    float mx0 = -1e30f, mx1 = -1e30f;
#pragma unroll
    for (int ni = 0; ni < 8; ni++) {
      int cg = kb * 64 + ni * 8 + tg * 2;
      float t0 = c[ni][0] * scale, t1 = c[ni][1] * scale;
      float t2 = c[ni][2] * scale, t3 = c[ni][3] * scale;
      if (msk) {
        if (cg > rg0) t0 = -1e30f;
        if (cg + 1 > rg0) t1 = -1e30f;
        if (cg > rg1) t2 = -1e30f;
        if (cg + 1 > rg1) t3 = -1e30f;
      }
      c[ni][0] = t0; c[ni][1] = t1; c[ni][2] = t2; c[ni][3] = t3;
      mx0 = fmaxf(mx0, fmaxf(t0, t1));
      mx1 = fmaxf(mx1, fmaxf(t2, t3));
    }
    mx0 = fmaxf(mx0, __shfl_xor_sync(0xffffffffu, mx0, 1));
    mx0 = fmaxf(mx0, __shfl_xor_sync(0xffffffffu, mx0, 2));
    mx1 = fmaxf(mx1, __shfl_xor_sync(0xffffffffu, mx1, 1));
    mx1 = fmaxf(mx1, __shfl_xor_sync(0xffffffffu, mx1, 2));

    float mn0 = fmaxf(m0, mx0), mn1 = fmaxf(m1, mx1);
    float corr0 = __expf(m0 - mn0), corr1 = __expf(m1 - mn1);
    m0 = mn0; m1 = mn1;
    float s0 = 0.f, s1 = 0.f;
#pragma unroll
    for (int ni = 0; ni < 8; ni++) {
      c[ni][0] = __expf(c[ni][0] - mn0);
      c[ni][1] = __expf(c[ni][1] - mn0);
      c[ni][2] = __expf(c[ni][2] - mn1);
      c[ni][3] = __expf(c[ni][3] - mn1);
      s0 += c[ni][0] + c[ni][1];
      s1 += c[ni][2] + c[ni][3];
    }
    s0 += __shfl_xor_sync(0xffffffffu, s0, 1);
    s0 += __shfl_xor_sync(0xffffffffu, s0, 2);
    s1 += __shfl_xor_sync(0xffffffffu, s1, 1);
    s1 += __shfl_xor_sync(0xffffffffu, s1, 2);
    l0 = l0 * corr0 + s0;
    l1 = l1 * corr1 + s1;

#pragma unroll
    for (int ni = 0; ni < 16; ni++) {
      o[ni][0] *= corr0; o[ni][1] *= corr0;
      o[ni][2] *= corr1; o[ni][3] *= corr1;
    }

    // O += P @ V (P from registers, V fragments via ldmatrix)
#pragma unroll
    for (int kc = 0; kc < 4; kc++) {
      float p00 = c[2 * kc][0], p01 = c[2 * kc][1];
      float p02 = c[2 * kc][2], p03 = c[2 * kc][3];
      float p10 = c[2 * kc + 1][0], p11 = c[2 * kc + 1][1];
      float p12 = c[2 * kc + 1][2], p13 = c[2 * kc + 1][3];
      uint32_t ap[4], apl[4];
      ap[0] = pack2bf(p00, p01);
      ap[1] = pack2bf(p02, p03);
      ap[2] = pack2bf(p10, p11);
      ap[3] = pack2bf(p12, p13);
      float h00 = __bfloat162float(__float2bfloat16(p00));
      float h01 = __bfloat162float(__float2bfloat16(p01));
      float h02 = __bfloat162float(__float2bfloat16(p02));
      float h03 = __bfloat162float(__float2bfloat16(p03));
      float h10 = __bfloat162float(__float2bfloat16(p10));
      float h11 = __bfloat162float(__float2bfloat16(p11));
      float h12 = __bfloat162float(__float2bfloat16(p12));
      float h13 = __bfloat162float(__float2bfloat16(p13));
      apl[0] = pack2bf(p00 - h00, p01 - h01);
      apl[1] = pack2bf(p02 - h02, p03 - h03);
      apl[2] = pack2bf(p10 - h10, p11 - h11);
      apl[3] = pack2bf(p12 - h12, p13 - h13);
#pragma unroll
      for (int pi = 0; pi < 8; pi++) {
        uint32_t va = vsb + (uint32_t)(((pi * 16 + b_row) * 72 +
                                        kc * 16 + b_ko) * 2);
        uint32_t bv[4], bvl[4];
        ldsm_x4(bv, va);
        ldsm_x4(bvl, va + 18432);
        mma16816(o[2 * pi], ap, bv);
        mma16816(o[2 * pi], apl, bv);
        mma16816(o[2 * pi], ap, bvl);
        mma16816(o[2 * pi + 1], ap, bv + 2);
        mma16816(o[2 * pi + 1], apl, bv + 2);
        mma16816(o[2 * pi + 1], ap, bvl + 2);
      }
    }
    __syncthreads();
  }

  const float inv0 = 1.f / l0, inv1 = 1.f / l1;
  const size_t row0 = (size_t)b * SEQ + qb * 128 + warp * 16 + g;
#pragma unroll
  for (int ni = 0; ni < 16; ni++) {
    int col = h * HD + ni * 8 + tg * 2;
    float v0 = o[ni][0] * inv0, v1 = o[ni][1] * inv0;
    float v2 = o[ni][2] * inv1, v3 = o[ni][3] * inv1;
    float h0 = __bfloat162float(__float2bfloat16(v0));
    float h1 = __bfloat162float(__float2bfloat16(v1));
    float h2 = __bfloat162float(__float2bfloat16(v2));
    float h3 = __bfloat162float(__float2bfloat16(v3));
    size_t i0 = row0 * HHD + col;
    size_t i1 = (row0 + 8) * HHD + col;
    *(uint32_t*)(Oh + i0) = pack2bf(v0, v1);
    *(uint32_t*)(Ol + i0) = pack2bf(v0 - h0, v1 - h1);
    *(uint32_t*)(Oh + i1) = pack2bf(v2, v3);
    *(uint32_t*)(Ol + i1) = pack2bf(v2 - h2, v3 - h3);
  }
}

// ---------------- launch -----------------------------------------------------
#define SYM(p, s)                          \
  do {                                     \
    void* _t;                              \
    cudaGetSymbolAddress(&_t, s);          \
    p = (decltype(p))_t;                   \
  } while (0)

extern "C" void kernel_launch(void* const* d_in, const int* in_sizes, int n_in,
                              void* d_out, int out_size) {
  const float* x = (const float*)d_in[0];
  const float* cosT = (const float*)d_in[1];
  const float* sinT = (const float*)d_in[2];
  const float* wq_down = (const float*)d_in[3];
  const float* wq_up = (const float*)d_in[4];
  const float* wkv_down = (const float*)d_in[5];
  const float* w_nope = (const float*)d_in[6];
  const float* w_rope = (const float*)d_in[7];
  const float* w_val = (const float*)d_in[8];
  const float* wo = (const float*)d_in[9];
  float* out = (float*)d_out;

  float *p_q, *p_kvup;
  SYM(p_q, g_q); SYM(p_kvup, g_kvup);

  __nv_bfloat16 *xh, *xl, *qkvh, *qkvl, *ath, *atl;
  __nv_bfloat16 *qah, *qal, *kah, *kal, *vth, *vtl;
  __nv_bfloat16 *wAh, *wAl, *wquh, *wqul, *wBh, *wBl, *woh, *wol;
  SYM(xh, g_x_h);   SYM(xl, g_x_l);
  SYM(qkvh, g_qkv_h); SYM(qkvl, g_qkv_l);
  SYM(ath, g_at_h); SYM(atl, g_at_l);
  SYM(qah, g_qa_h); SYM(qal, g_qa_l); SYM(kah, g_ka_h); SYM(kal, g_ka_l);
  SYM(vth, g_vt_h); SYM(vtl, g_vt_l);
  SYM(wAh, g_wA_h); SYM(wAl, g_wA_l); SYM(wquh, g_wqu_h); SYM(wqul, g_wqu_l);
  SYM(wBh, g_wB_h); SYM(wBl, g_wB_l); SYM(woh, g_wo_h);  SYM(wol, g_wo_l);

  cudaFuncSetAttribute(mma_gemm_kernel,
                       cudaFuncAttributeMaxDynamicSharedMemorySize, MG_SMEM);
  cudaFuncSetAttribute(flash_mma_kernel,
                       cudaFuncAttributeMaxDynamicSharedMemorySize,
                       FLASH_MMA_SMEM);

  dim3 tsb(32, 8);
  // input/weight conversions (wA = [wq_down | wkv_down], wB = [wn|wr|wv])
  split_kernel<<<(NT * DIM / 4) / 256, 256>>>(x, xh, xl, NT * DIM / 4);
  tsplit_kernel<<<dim3(QR / 32, DIM / 32), tsb>>>(wq_down, wAh, wAl, DIM, QR);
  tsplit_kernel<<<dim3(KVR / 32, DIM / 32), tsb>>>(
      wkv_down, wAh + (size_t)QR * DIM, wAl + (size_t)QR * DIM, DIM, KVR);
  tsplit_kernel<<<dim3(HHD / 32, QR / 32), tsb>>>(wq_up, wquh, wqul, QR, HHD);
  tsplit_kernel<<<dim3(QR / 32, KVR / 32), tsb>>>(w_nope, wBh, wBl, KVR, QR);
  tsplit_kernel<<<dim3(512 / 32, KVR / 32), tsb>>>(
      w_rope, wBh + (size_t)QR * KVR, wBl + (size_t)QR * KVR, KVR, 512);
  tsplit_kernel<<<dim3(HHD / 32, KVR / 32), tsb>>>(
      w_val, wBh + (size_t)2048 * KVR, wBl + (size_t)2048 * KVR, KVR, HHD);
  tsplit_kernel<<<dim3(DIM / 32, HHD / 32), tsb>>>(wo, woh, wol, HHD, DIM);

  // G1: x @ [wq_down|wkv_down] -> qkv hi/lo bf16 [NT, 2048]
  mma_gemm_kernel<<<dim3(2048 / 128, NT / 128), 256, MG_SMEM>>>(
      xh, xl, wAh, wAl, nullptr, qkvh, qkvl, 2048, DIM, DIM, DIM, 1);
  // G2: qlat @ wq_up -> p_q fp32
  mma_gemm_kernel<<<dim3(HHD / 128, NT / 128), 256, MG_SMEM>>>(
      qkvh, qkvl, wquh, wqul, p_q, nullptr, nullptr, HHD, QR, 2048, QR, 0);
  // G3: kv @ [wn|wr|wv] -> p_kvup fp32 [NT, 4096]
  mma_gemm_kernel<<<dim3(KVUP / 128, NT / 128), 256, MG_SMEM>>>(
      qkvh + QR, qkvl + QR, wBh, wBl, p_kvup, nullptr, nullptr, KVUP, KVR,
      2048, KVR, 0);

  // attention operand prep
  q_prep_kernel<<<(BH * SEQ * 64) / 256, 256>>>(p_q, qah, qal, cosT, sinT);
  k_prep_kernel<<<(BH * SEQ * 64) / 256, 256>>>(p_kvup, kah, kal, cosT, sinT);
  vt_prep_kernel<<<dim3(SEQ / 32, HD / 32, BH), tsb>>>(p_kvup, vth, vtl);

  // attention (writes bf16 hi/lo directly)
  flash_mma_kernel<<<dim3(SEQ / 128, BH), 256, FLASH_MMA_SMEM>>>(
      qah, qal, kah, kal, vth, vtl, ath, atl);

  // G4: attn @ wo -> out fp32
  mma_gemm_kernel<<<dim3(DIM / 128, NT / 128), 256, MG_SMEM>>>(
      ath, atl, woh, wol, out, nullptr, nullptr, DIM, HHD, HHD, HHD, 0);
}